// round 6
// baseline (speedup 1.0000x reference)
#include <cuda_runtime.h>
#include <cstdint>

// SegmentedPolynomialIndexedLinear: y[z] = coeff * x[z] @ W[idx[z]]
//   C=8, U=V=512, Z=32768, fp32. Sorted idx -> per-tile group loop w/ masking.
//
// mma.sync m16n8k8 tf32 with fragment-ready smem layouts:
//  - k permuted within each 16-k tile (pos = 4*(k%4)+k/4) so one LDS.128
//    fetches a thread's 4 frag regs {k=lq, lq+4, lq+8, lq+12}.
//  - B (=W[g]) pre-transposed+permuted+tf32-converted into d_WTp by a tiny
//    pre-kernel; main-kernel B path = cp.async fill + 4 LDS.128/k-tile, 0 cvt.
//  - A filled LDG->cvt->scatter STS with XOR granule swizzle (reads
//    conflict-free, stores 2-way); cvt once per element at fill.
//  - 3-stage pipeline, ONE __syncthreads per k-tile, empty commits keep
//    cp.async group counting exact.

namespace {
constexpr int Cc = 8, Uc = 512, Vc = 512, Zc = 32768;
constexpr int BM = 128, BN = 128, BK = 16;
constexpr int NT = 256;
constexpr int KT = Uc / BK;        // 32
constexpr int STG = BM * BK * 4;   // 8192 B per stage (A or B tile, tf32 bits)
constexpr int OFF_A   = 0;
constexpr int OFF_B   = 3 * STG;   // 24576
constexpr int OFF_IDX = 6 * STG;   // 49152
constexpr int SMEM_TOTAL = OFF_IDX + BM * 4;  // 49664
}

__device__ uint32_t d_WTp[(size_t)Cc * Uc * Vc];  // tf32 bits, [c][n][perm(k)]

#define DEVFN __device__ __forceinline__

DEVFN uint32_t smem_u32(const void* p) {
    uint32_t a;
    asm("{ .reg .u64 t; cvta.to.shared.u64 t, %1; cvt.u32.u64 %0, t; }"
        : "=r"(a) : "l"(p));
    return a;
}
DEVFN uint32_t f2tf(float f) {
    uint32_t u;
    asm("cvt.rna.tf32.f32 %0, %1;" : "=r"(u) : "f"(f));
    return u;
}
DEVFN void cp16(uint32_t dst, const void* src) {
    asm volatile("cp.async.cg.shared.global [%0], [%1], 16;"
                 :: "r"(dst), "l"(src) : "memory");
}
DEVFN void cp_commit() { asm volatile("cp.async.commit_group;" ::: "memory"); }
template <int N> DEVFN void cp_wait() {
    asm volatile("cp.async.wait_group %0;" :: "n"(N) : "memory");
}
DEVFN void sts32(uint32_t a, uint32_t v) {
    asm volatile("st.shared.b32 [%0], %1;" :: "r"(a), "r"(v) : "memory");
}
DEVFN void lds128(uint32_t* r, uint32_t a) {
    asm volatile("ld.shared.v4.b32 {%0,%1,%2,%3}, [%4];"
                 : "=r"(r[0]), "=r"(r[1]), "=r"(r[2]), "=r"(r[3]) : "r"(a));
}
DEVFN void mma_tf32(float* d, const uint32_t* a, const uint32_t* b) {
    asm volatile(
        "mma.sync.aligned.m16n8k8.row.col.f32.tf32.tf32.f32 "
        "{%0,%1,%2,%3}, {%4,%5,%6,%7}, {%8,%9}, {%0,%1,%2,%3};"
        : "+f"(d[0]), "+f"(d[1]), "+f"(d[2]), "+f"(d[3])
        : "r"(a[0]), "r"(a[1]), "r"(a[2]), "r"(a[3]), "r"(b[0]), "r"(b[1]));
}

// ---- pre-kernel: d_WTp[c][n][perm(u)] = tf32(W[c][u][n]) --------------------
__global__ void prep_w(const float* __restrict__ W) {
    __shared__ float t[32][33];
    const int c = blockIdx.z, v0 = blockIdx.x * 32, u0 = blockIdx.y * 32;
    const int tx = threadIdx.x, ty = threadIdx.y;
    const float*  Wc = W + (size_t)c * Uc * Vc;
    uint32_t*     Oc = d_WTp + (size_t)c * Uc * Vc;
#pragma unroll
    for (int j = 0; j < 4; ++j)
        t[ty + 8 * j][tx] = Wc[(size_t)(u0 + ty + 8 * j) * Vc + v0 + tx];
    __syncthreads();
    const int u   = u0 + tx;
    const int pos = (u & ~15) + 4 * (u & 3) + ((u >> 2) & 3);
#pragma unroll
    for (int j = 0; j < 4; ++j)
        Oc[(size_t)(v0 + ty + 8 * j) * Uc + pos] = f2tf(t[tx][ty + 8 * j]);
}

// ---- fill helpers -----------------------------------------------------------
DEVFN void loadA(const float* xr, int kt, int sf, bool ok, float4* v) {
    if (ok) {
        v[0] = *(const float4*)(xr + kt * 16 + 8 * sf);
        v[1] = *(const float4*)(xr + kt * 16 + 8 * sf + 4);
    } else {
        v[0] = make_float4(0.f, 0.f, 0.f, 0.f);
        v[1] = make_float4(0.f, 0.f, 0.f, 0.f);
    }
}
DEVFN void stsA(uint32_t base, int rf, int sf, int swf, const float4* v) {
#pragma unroll
    for (int c4 = 0; c4 < 2; ++c4) {
        const float* p = (const float*)&v[c4];
        const int m = 2 * sf + c4;
#pragma unroll
        for (int j = 0; j < 4; ++j)
            sts32(base + (uint32_t)((rf * 16 + 4 * (j ^ swf) + m) * 4),
                  f2tf(p[j]));
    }
}
DEVFN void cpB(const uint32_t* wb, int kt, uint32_t dstBase, int rf, int sf) {
#pragma unroll
    for (int c4 = 0; c4 < 2; ++c4) {
        const int q = 2 * sf + c4;
        cp16(dstBase + (uint32_t)((rf * 16 + 4 * q) * 4),
             wb + (size_t)rf * Uc + kt * 16 + 4 * q);
    }
}

// ---- main kernel ------------------------------------------------------------
__global__ void __launch_bounds__(NT, 2)
grouped_mma2(const float* __restrict__ X,
             const int*   __restrict__ IDX,
             const float* __restrict__ COEF,
             float*       __restrict__ Y)
{
    extern __shared__ __align__(16) char smem[];
    const uint32_t sb = smem_u32(smem);
    int* sidx = (int*)(smem + OFF_IDX);

    const int tid = threadIdx.x;
    const int m0 = blockIdx.y * BM, n0 = blockIdx.x * BN;
    if (tid < BM) sidx[tid] = IDX[m0 + tid];
    __syncthreads();
    const int g0 = sidx[0], g1 = sidx[BM - 1];

    const int wid = tid >> 5, lane = tid & 31;
    const int wm = wid >> 2, wn = wid & 3, lr = lane >> 2, lq = lane & 3;

    // fill mapping: thread -> row rf, k-half sf (2 float4 chunks per k-tile)
    const int rf = tid >> 1, sf = tid & 1;
    const int swf = (rf >> 1) & 3;
    const float* xr = X + (size_t)(m0 + rf) * Uc;

    const uint32_t aStg[3] = {sb + OFF_A, sb + OFF_A + STG, sb + OFF_A + 2 * STG};
    const uint32_t bStg[3] = {sb + OFF_B, sb + OFF_B + STG, sb + OFF_B + 2 * STG};
    const uint32_t colA = (uint32_t)(4 * (lq ^ ((lr >> 1) & 3))) * 4;

    float acc[4][4][4];
#pragma unroll
    for (int mt = 0; mt < 4; ++mt)
#pragma unroll
        for (int nt = 0; nt < 4; ++nt)
#pragma unroll
            for (int e = 0; e < 4; ++e) acc[mt][nt][e] = 0.f;

    for (int g = g0; g <= g1; ++g) {
        const bool ok = (sidx[rf] == g);
        const uint32_t* wb = d_WTp + (size_t)g * Uc * Vc + (size_t)n0 * Uc;

        float4 cur[2], nxt[2];
        loadA(xr, 0, sf, ok, cur);
        stsA(aStg[0], rf, sf, swf, cur);
        loadA(xr, 1, sf, ok, nxt);
        cpB(wb, 0, bStg[0], rf, sf); cp_commit();
        cpB(wb, 1, bStg[1], rf, sf); cp_commit();

#pragma unroll 1
        for (int kt = 0; kt < KT; ++kt) {
            cp_wait<1>();
            __syncthreads();

            // pipeline maintenance (targets are one-sync-old stages: safe)
            if (kt + 1 < KT) stsA(aStg[(kt + 1) % 3], rf, sf, swf, nxt);
            if (kt + 2 < KT) {
                loadA(xr, kt + 2, sf, ok, nxt);
                cpB(wb, kt + 2, bStg[(kt + 2) % 3], rf, sf);
            }
            cp_commit();  // always (empty ok) -> wait<1> math stays exact

            const uint32_t aB = aStg[kt % 3], bB = bStg[kt % 3];
            uint32_t bn[4][4];
#pragma unroll
            for (int nt = 0; nt < 4; ++nt) {
                const int n = wn * 32 + nt * 8 + lr;
                lds128(bn[nt], bB + (uint32_t)((n * 16 + 4 * lq) * 4));
            }
#pragma unroll
            for (int mt = 0; mt < 4; ++mt) {
                const int r = wm * 64 + mt * 16 + lr;
                uint32_t ar0[4], ar1[4];
                lds128(ar0, aB + (uint32_t)(r * 64) + colA);
                lds128(ar1, aB + (uint32_t)((r + 8) * 64) + colA);
#pragma unroll
                for (int nt = 0; nt < 4; ++nt) {
                    {
                        uint32_t a[4] = {ar0[0], ar1[0], ar0[1], ar1[1]};
                        uint32_t b[2] = {bn[nt][0], bn[nt][1]};
                        mma_tf32(acc[mt][nt], a, b);
                    }
                    {
                        uint32_t a[4] = {ar0[2], ar1[2], ar0[3], ar1[3]};
                        uint32_t b[2] = {bn[nt][2], bn[nt][3]};
                        mma_tf32(acc[mt][nt], a, b);
                    }
                }
            }
        }
        __syncthreads();  // protect stages before next g's prologue refill
    }

    const float scale = COEF[0];
#pragma unroll
    for (int mt = 0; mt < 4; ++mt) {
        const int r0 = m0 + wm * 64 + mt * 16 + lr;
#pragma unroll
        for (int nt = 0; nt < 4; ++nt) {
            const int col = n0 + wn * 32 + nt * 8 + 2 * lq;
            float2 v0, v1;
            v0.x = acc[mt][nt][0] * scale;
            v0.y = acc[mt][nt][1] * scale;
            v1.x = acc[mt][nt][2] * scale;
            v1.y = acc[mt][nt][3] * scale;
            *(float2*)(Y + (size_t)r0 * Vc + col)       = v0;
            *(float2*)(Y + (size_t)(r0 + 8) * Vc + col) = v1;
        }
    }
}

// ---- launcher ---------------------------------------------------------------
extern "C" void kernel_launch(void* const* d_in, const int* in_sizes, int n_in,
                              void* d_out, int out_size)
{
    const float* w    = nullptr;
    const float* x    = nullptr;
    const int*   idx  = nullptr;
    const float* coef = nullptr;
    for (int i = 0; i < n_in; ++i) {
        const long long sz = in_sizes[i];
        if      (sz == (long long)Cc * Uc * Vc) w    = (const float*)d_in[i];
        else if (sz == (long long)Zc * Uc)      x    = (const float*)d_in[i];
        else if (sz == (long long)Zc)           idx  = (const int*)d_in[i];
        else if (sz == 1)                       coef = (const float*)d_in[i];
    }
    if (!w    && n_in > 0) w    = (const float*)d_in[0];
    if (!x    && n_in > 1) x    = (const float*)d_in[1];
    if (!idx  && n_in > 2) idx  = (const int*)d_in[2];
    if (!coef && n_in > 3) coef = (const float*)d_in[3];

    float* y = (float*)d_out;

    prep_w<<<dim3(Vc / 32, Uc / 32, Cc), dim3(32, 8)>>>(w);

    cudaFuncSetAttribute(grouped_mma2,
                         cudaFuncAttributeMaxDynamicSharedMemorySize, SMEM_TOTAL);
    grouped_mma2<<<dim3(Vc / BN, Zc / BM), NT, SMEM_TOTAL>>>(x, idx, coef, y);
}

// round 9
// speedup vs baseline: 1.1857x; 1.1857x over previous
#include <cuda_runtime.h>
#include <cstdint>

// SegmentedPolynomialIndexedLinear: y[z] = coeff * x[z] @ W[idx[z]]
//   C=8, U=V=512, Z=32768, fp32, sorted idx.
//
// Round 7/8/9: round-4 skeleton (cp.async fills, 2-stage, 2 barriers/k-tile):
//  - B from prep_w'd d_WTp[c][n][perm(k)] (tf32-rna bits): cp.async + 8
//    LDS.128 per k-tile, zero cvt (mapping validated: rel_err identical r4/r6).
//  - A: cp.async zfill-masked into k-major stride-20 rows (conflict-free
//    LDS.32 reads), cvt.rna at use (identical arithmetic to round 4).
//  - Warp grid 4x2 (warp tile 32x64): halves A fragment traffic.
// Issue budget/warp/k-tile: 16 LDS.32 + 16 cvt + 8 LDS.128 + 32 MMA ~= 82
// (round 4: ~140) -> tensor pipe becomes the binder.

namespace {
constexpr int Cc = 8, Uc = 512, Vc = 512, Zc = 32768;
constexpr int BM = 128, BN = 128, BK = 16;
constexpr int NT = 256;
constexpr int KT = Uc / BK;   // 32
constexpr int ASTRIDE = 20;   // words per A row (80B, 16B-aligned, %32 permutes)
}

__device__ uint32_t d_WTp[(size_t)Cc * Uc * Vc];  // tf32 bits, [c][n][perm(k)]

#define DEVFN __device__ __forceinline__

DEVFN uint32_t smem_u32(const void* p) {
    uint32_t a;
    asm("{ .reg .u64 t; cvta.to.shared.u64 t, %1; cvt.u32.u64 %0, t; }"
        : "=r"(a) : "l"(p));
    return a;
}
DEVFN uint32_t f2tf(float f) {
    uint32_t u;
    asm("cvt.rna.tf32.f32 %0, %1;" : "=r"(u) : "f"(f));
    return u;
}
DEVFN void cp16z(uint32_t dst, const void* src, int srcbytes) {
    asm volatile("cp.async.cg.shared.global [%0], [%1], 16, %2;"
                 :: "r"(dst), "l"(src), "r"(srcbytes) : "memory");
}
DEVFN void cp16(uint32_t dst, const void* src) {
    asm volatile("cp.async.cg.shared.global [%0], [%1], 16;"
                 :: "r"(dst), "l"(src) : "memory");
}
DEVFN void cp_commit() { asm volatile("cp.async.commit_group;" ::: "memory"); }
template <int N> DEVFN void cp_wait() {
    asm volatile("cp.async.wait_group %0;" :: "n"(N) : "memory");
}
DEVFN void lds128(uint32_t* r, uint32_t a) {
    asm volatile("ld.shared.v4.b32 {%0,%1,%2,%3}, [%4];"
                 : "=r"(r[0]), "=r"(r[1]), "=r"(r[2]), "=r"(r[3]) : "r"(a));
}
DEVFN void mma_tf32(float* d, const uint32_t* a, const uint32_t* b) {
    asm volatile(
        "mma.sync.aligned.m16n8k8.row.col.f32.tf32.tf32.f32 "
        "{%0,%1,%2,%3}, {%4,%5,%6,%7}, {%8,%9}, {%0,%1,%2,%3};"
        : "+f"(d[0]), "+f"(d[1]), "+f"(d[2]), "+f"(d[3])
        : "r"(a[0]), "r"(a[1]), "r"(a[2]), "r"(a[3]), "r"(b[0]), "r"(b[1]));
}

// ---- pre-kernel: d_WTp[c][n][perm(u)] = tf32_rna(W[c][u][n]) ----------------
__global__ void prep_w(const float* __restrict__ W) {
    __shared__ float t[32][33];
    const int c = blockIdx.z, v0 = blockIdx.x * 32, u0 = blockIdx.y * 32;
    const int tx = threadIdx.x, ty = threadIdx.y;
    const float* Wc = W + (size_t)c * Uc * Vc;
    uint32_t*    Oc = d_WTp + (size_t)c * Uc * Vc;
#pragma unroll
    for (int j = 0; j < 4; ++j)
        t[ty + 8 * j][tx] = Wc[(size_t)(u0 + ty + 8 * j) * Vc + v0 + tx];
    __syncthreads();
    const int u   = u0 + tx;
    const int pos = (u & ~15) + 4 * (u & 3) + ((u >> 2) & 3);
#pragma unroll
    for (int j = 0; j < 4; ++j)
        Oc[(size_t)(v0 + ty + 8 * j) * Uc + pos] = f2tf(t[tx][ty + 8 * j]);
}

// ---- main kernel ------------------------------------------------------------
__global__ void __launch_bounds__(NT, 2)
grouped_mma3(const float* __restrict__ X,
             const int*   __restrict__ IDX,
             const float* __restrict__ COEF,
             float*       __restrict__ Y)
{
    __shared__ float    As[2][BM][ASTRIDE];  // k-major fp32, 80B rows
    __shared__ uint32_t Bs[2][BN][16];       // tf32 bits, perm(k)
    __shared__ int      sidx[BM];

    const int tid = threadIdx.x;
    const int m0 = blockIdx.y * BM, n0 = blockIdx.x * BN;
    if (tid < BM) sidx[tid] = IDX[m0 + tid];
    __syncthreads();
    const int g0 = sidx[0], g1 = sidx[BM - 1];

    const int wid = tid >> 5, lane = tid & 31;
    const int wm = wid >> 1, wn = wid & 1;     // warp grid 4 x 2, tile 32 x 64
    const int lr = lane >> 2, lq = lane & 3;

    // fill mapping: thread -> row rf (0..127), half sf (2 x 16B chunks each)
    const int rf = tid >> 1, sf = tid & 1;
    const float* xr = X + (size_t)(m0 + rf) * Uc;

    const uint32_t aD[2] = {smem_u32(&As[0][rf][0]), smem_u32(&As[1][rf][0])};
    const uint32_t bD[2] = {smem_u32(&Bs[0][rf][0]), smem_u32(&Bs[1][rf][0])};

    float acc[2][8][4];
#pragma unroll
    for (int mt = 0; mt < 2; ++mt)
#pragma unroll
        for (int nt = 0; nt < 8; ++nt)
#pragma unroll
            for (int e = 0; e < 4; ++e) acc[mt][nt][e] = 0.f;

    for (int g = g0; g <= g1; ++g) {
        const int asz = (sidx[rf] == g) ? 16 : 0;
        const uint32_t* wb = d_WTp + (size_t)g * Uc * Vc + (size_t)n0 * Uc
                           + (size_t)rf * Uc;

        // prologue: stage 0 = k-tile 0
#pragma unroll
        for (int c4 = 0; c4 < 2; ++c4) {
            const int q = 2 * sf + c4;
            cp16z(aD[0] + q * 16, xr + 4 * q, asz);
            cp16 (bD[0] + q * 16, wb + 4 * q);
        }
        cp_commit();

#pragma unroll 1
        for (int kt = 0; kt < KT; ++kt) {
            if (kt + 1 < KT) {
                const int k0 = (kt + 1) * BK;
                const int st = (kt + 1) & 1;
#pragma unroll
                for (int c4 = 0; c4 < 2; ++c4) {
                    const int q = 2 * sf + c4;
                    cp16z(aD[st] + q * 16, xr + k0 + 4 * q, asz);
                    cp16 (bD[st] + q * 16, wb + k0 + 4 * q);
                }
                cp_commit();
                cp_wait<1>();
            } else {
                cp_wait<0>();
            }
            __syncthreads();

            const int buf = kt & 1;
            uint32_t bn[8][4];
#pragma unroll
            for (int nt = 0; nt < 8; ++nt)
                lds128(bn[nt],
                       smem_u32(&Bs[buf][wn * 64 + nt * 8 + lr][4 * lq]));
#pragma unroll
            for (int mt = 0; mt < 2; ++mt) {
                const int r = wm * 32 + mt * 16 + lr;
                uint32_t aw[8];
                aw[0] = f2tf(As[buf][r][lq]);
                aw[1] = f2tf(As[buf][r + 8][lq]);
                aw[2] = f2tf(As[buf][r][lq + 4]);
                aw[3] = f2tf(As[buf][r + 8][lq + 4]);
                aw[4] = f2tf(As[buf][r][lq + 8]);
                aw[5] = f2tf(As[buf][r + 8][lq + 8]);
                aw[6] = f2tf(As[buf][r][lq + 12]);
                aw[7] = f2tf(As[buf][r + 8][lq + 12]);
#pragma unroll
                for (int nt = 0; nt < 8; ++nt) {
                    mma_tf32(acc[mt][nt], aw,     bn[nt]);       // k 0..7
                    mma_tf32(acc[mt][nt], aw + 4, bn[nt] + 2);   // k 8..15
                }
            }
            __syncthreads();
        }
    }

    const float scale = COEF[0];
#pragma unroll
    for (int mt = 0; mt < 2; ++mt) {
        const int r0 = m0 + wm * 32 + mt * 16 + lr;
#pragma unroll
        for (int nt = 0; nt < 8; ++nt) {
            const int col = n0 + wn * 64 + nt * 8 + 2 * lq;
            float2 v0, v1;
            v0.x = acc[mt][nt][0] * scale;
            v0.y = acc[mt][nt][1] * scale;
            v1.x = acc[mt][nt][2] * scale;
            v1.y = acc[mt][nt][3] * scale;
            *(float2*)(Y + (size_t)r0 * Vc + col)       = v0;
            *(float2*)(Y + (size_t)(r0 + 8) * Vc + col) = v1;
        }
    }
}

// ---- launcher ---------------------------------------------------------------
extern "C" void kernel_launch(void* const* d_in, const int* in_sizes, int n_in,
                              void* d_out, int out_size)
{
    const float* w    = nullptr;
    const float* x    = nullptr;
    const int*   idx  = nullptr;
    const float* coef = nullptr;
    for (int i = 0; i < n_in; ++i) {
        const long long sz = in_sizes[i];
        if      (sz == (long long)Cc * Uc * Vc) w    = (const float*)d_in[i];
        else if (sz == (long long)Zc * Uc)      x    = (const float*)d_in[i];
        else if (sz == (long long)Zc)           idx  = (const int*)d_in[i];
        else if (sz == 1)                       coef = (const float*)d_in[i];
    }
    if (!w    && n_in > 0) w    = (const float*)d_in[0];
    if (!x    && n_in > 1) x    = (const float*)d_in[1];
    if (!idx  && n_in > 2) idx  = (const int*)d_in[2];
    if (!coef && n_in > 3) coef = (const float*)d_in[3];

    float* y = (float*)d_out;

    prep_w<<<dim3(Vc / 32, Uc / 32, Cc), dim3(32, 8)>>>(w);
    grouped_mma3<<<dim3(Vc / BN, Zc / BM), NT>>>(x, idx, coef, y);
}